// round 15
// baseline (speedup 1.0000x reference)
#include <cuda_runtime.h>
#include <cuda_fp16.h>
#include <cstdint>
#include <math.h>

#define B_   4096
#define N_   32768
#define D_   1024
#define BM   128
#define BN   128
#define KC   64                  // K elems per chunk (64 fp16 = 128 B row)
#define NCH  (D_ / KC)           // 16
#define NBLK (N_ / BN)           // 256
#define BBLK (B_ / BM)           // 32

#define TILE_B   16384           // one chunk-tile: 128 rows x 128 B (swizzled)
#define STAGE_B  (2 * TILE_B)    // A + B chunk = 32 KB
#define MBAR_OFF (2 * STAGE_B)   // 65536
#define SMEM_DYN (MBAR_OFF + 64)

// ---------------- device-global scratch ------------------------------------
// qh/kh stored TILED+SWIZZLED: tile t = (block*16 + chunk) is 16 KB contiguous;
// within a tile: 128 rows x 128 B with SW128 swizzle.
__device__ float  g_qinv[B_];
__device__ float  g_kinv[N_];
__device__ __align__(256) __half g_qh[(size_t)B_ * D_];
__device__ __align__(256) __half g_kh[(size_t)N_ * D_];
__device__ float4 g_topA[(size_t)B_ * NBLK];  // v0,i0,v1,i1
__device__ float2 g_topB[(size_t)B_ * NBLK];  // v2,i2
__device__ float2 g_ms  [(size_t)B_ * NBLK];  // sum,sumsq
__device__ float  g_var[B_];

// ---------------- helpers ---------------------------------------------------
__device__ __forceinline__ uint32_t smem_u32(const void* p) {
    uint32_t a;
    asm("{ .reg .u64 t; cvta.to.shared.u64 t, %1; cvt.u32.u64 %0, t; }" : "=r"(a) : "l"(p));
    return a;
}
__device__ __forceinline__ void ldsm4(uint32_t* r, uint32_t addr) {
    asm volatile("ldmatrix.sync.aligned.m8n8.x4.shared.b16 {%0,%1,%2,%3}, [%4];"
                 : "=r"(r[0]), "=r"(r[1]), "=r"(r[2]), "=r"(r[3]) : "r"(addr));
}
__device__ __forceinline__ void mma16816(float* c, const uint32_t* a, const uint32_t* b) {
    asm volatile("mma.sync.aligned.m16n8k16.row.col.f32.f16.f16.f32 "
                 "{%0,%1,%2,%3}, {%4,%5,%6,%7}, {%8,%9}, {%0,%1,%2,%3};"
                 : "+f"(c[0]), "+f"(c[1]), "+f"(c[2]), "+f"(c[3])
                 : "r"(a[0]), "r"(a[1]), "r"(a[2]), "r"(a[3]), "r"(b[0]), "r"(b[1]));
}
__device__ __forceinline__ void mbar_init(uint32_t a, uint32_t cnt) {
    asm volatile("mbarrier.init.shared.b64 [%0], %1;" :: "r"(a), "r"(cnt) : "memory");
}
__device__ __forceinline__ void mbar_expect_tx(uint32_t a, uint32_t bytes) {
    asm volatile("mbarrier.arrive.expect_tx.shared.b64 _, [%0], %1;"
                 :: "r"(a), "r"(bytes) : "memory");
}
__device__ __forceinline__ void mbar_arrive(uint32_t a) {
    asm volatile("mbarrier.arrive.shared.b64 _, [%0];" :: "r"(a) : "memory");
}
__device__ __forceinline__ void mbar_wait(uint32_t a, uint32_t parity) {
    uint32_t done;
    asm volatile("{\n\t.reg .pred p;\n\t"
                 "mbarrier.try_wait.parity.acquire.cta.shared::cta.b64 p, [%1], %2;\n\t"
                 "selp.b32 %0, 1, 0, p;\n\t}"
                 : "=r"(done) : "r"(a), "r"(parity) : "memory");
    if (!done) {
        asm volatile("{\n\t.reg .pred P;\n\tWL_%=:\n\t"
                     "mbarrier.try_wait.parity.acquire.cta.shared::cta.b64 P, [%0], %1, 0x989680;\n\t"
                     "@P bra.uni WD_%=;\n\tbra.uni WL_%=;\n\tWD_%=:\n\t}"
                     :: "r"(a), "r"(parity) : "memory");
    }
}
__device__ __forceinline__ void bulk_ld(uint32_t dst, const void* src, uint32_t bytes,
                                        uint32_t mbar) {
    asm volatile("cp.async.bulk.shared::cluster.global.mbarrier::complete_tx::bytes "
                 "[%0], [%1], %2, [%3];"
                 :: "r"(dst), "l"(src), "r"(bytes), "r"(mbar) : "memory");
}
__device__ __forceinline__ void top3_ins(float v, int i,
                                         float& v0, int& i0, float& v1, int& i1,
                                         float& v2, int& i2) {
    if (v > v0)      { v2 = v1; i2 = i1; v1 = v0; i1 = i0; v0 = v; i0 = i; }
    else if (v > v1) { v2 = v1; i2 = i1; v1 = v;  i1 = i; }
    else if (v > v2) { v2 = v;  i2 = i; }
}

// ---------------------------------------------------------------------------
// Kernel 1: prep -> inv norm + fp16 normalized rows in TILED+SWIZZLED layout
// ---------------------------------------------------------------------------
__global__ void prep_kernel(const float* __restrict__ x, float* __restrict__ inv_out,
                            __half* __restrict__ h_out)
{
    const int row = blockIdx.x;
    const int tid = threadIdx.x;   // 256
    float4 v = reinterpret_cast<const float4*>(x + (size_t)row * D_)[tid];
    float s = v.x * v.x + v.y * v.y + v.z * v.z + v.w * v.w;
    __shared__ float sm[256];
    sm[tid] = s;
    __syncthreads();
    for (int o = 128; o > 0; o >>= 1) {
        if (tid < o) sm[tid] += sm[tid + o];
        __syncthreads();
    }
    const float inv = 1.0f / fmaxf(sqrtf(sm[0]), 1e-12f);
    if (tid == 0) inv_out[row] = inv;

    __half2 h0 = __floats2half2_rn(v.x * inv, v.y * inv);
    __half2 h1 = __floats2half2_rn(v.z * inv, v.w * inv);
    uint2 pk;
    pk.x = *reinterpret_cast<uint32_t*>(&h0);
    pk.y = *reinterpret_cast<uint32_t*>(&h1);

    const int e0   = 4 * tid;
    const int c    = e0 >> 6;
    const int j    = e0 & 63;
    const int blk  = row >> 7;
    const int rloc = row & 127;
    uint32_t boff = (uint32_t)(rloc * 128 + j * 2);
    uint32_t sw   = boff ^ ((boff >> 3) & 0x70);
    char* dst = (char*)h_out + ((size_t)(blk * NCH + c) * TILE_B + sw);
    *reinterpret_cast<uint2*>(dst) = pk;
}

// ---------------------------------------------------------------------------
// Kernel 2: mma.sync fp16 GEMM, 128x128 tile, 4 warps @ 64x64, 3 CTAs/SM.
//           Producer-consumer mainloop: full/empty mbarrier pairs, NO
//           __syncthreads per chunk -> warps may skew across chunks.
// ---------------------------------------------------------------------------
__global__ __launch_bounds__(128, 3)
void sim_kernel()
{
    extern __shared__ char dynsmem[];
    const uint32_t sbase = smem_u32(dynsmem);

    const int tid = threadIdx.x;    // 128
    const int l   = tid & 31;
    const int wid = tid >> 5;       // 0..3
    const int wm  = wid >> 1;       // 0..1 -> 64-row half
    const int wn  = wid & 1;        // 0..1 -> 64-col half
    const int nblk = blockIdx.x;
    const int bblk = blockIdx.y;

    const char* srcA = (const char*)g_qh + (size_t)bblk * NCH * TILE_B;
    const char* srcB = (const char*)g_kh + (size_t)nblk * NCH * TILE_B;

    const uint32_t full0  = sbase + MBAR_OFF;
    const uint32_t full1  = sbase + MBAR_OFF + 8;
    const uint32_t empty0 = sbase + MBAR_OFF + 16;
    const uint32_t empty1 = sbase + MBAR_OFF + 24;

    if (tid == 0) {
        mbar_init(full0, 1);
        mbar_init(full1, 1);
        mbar_init(empty0, 4);   // one arrival per warp
        mbar_init(empty1, 4);
    }
    __syncthreads();

    auto issue = [&](int c) {
        const uint32_t st  = sbase + (c & 1) * STAGE_B;
        const uint32_t mbn = (c & 1) ? full1 : full0;
        mbar_expect_tx(mbn, STAGE_B);
        bulk_ld(st,          srcA + (size_t)c * TILE_B, TILE_B, mbn);
        bulk_ld(st + TILE_B, srcB + (size_t)c * TILE_B, TILE_B, mbn);
    };

    if (tid == 0) { issue(0); issue(1); }   // stages start free

    // ---- per-lane ldmatrix offsets ----------------------------------------
    const uint32_t rowA = l & 15;
    const uint32_t acs  = (l >> 4) * 16;
    const uint32_t xa   = (rowA & 7) << 4;
    const uint32_t aoff = rowA * 128 + (uint32_t)wm * 8192;   // wm*64 rows

    const uint32_t rowB = (l & 7) + ((l >> 4) << 3);
    const uint32_t bcs  = ((l >> 3) & 1) * 16;
    const uint32_t xb   = (rowB & 7) << 4;
    const uint32_t boff = rowB * 128 + (uint32_t)wn * 8192;   // wn*64 rows

    float acc[4][8][4];
#pragma unroll
    for (int m = 0; m < 4; m++)
#pragma unroll
        for (int n = 0; n < 8; n++)
#pragma unroll
            for (int e = 0; e < 4; e++) acc[m][n][e] = 0.f;

    int fpar[2] = {0, 0};

    for (int c = 0; c < NCH; c++) {
        const int st = c & 1;
        const uint32_t fullb  = st ? full1 : full0;
        const uint32_t emptyb = st ? empty1 : empty0;

        mbar_wait(fullb, fpar[st]);   // data for chunk c ready
        fpar[st] ^= 1;

        const uint32_t TBa = sbase + st * STAGE_B + aoff;
        const uint32_t TBb = sbase + st * STAGE_B + TILE_B + boff;

#pragma unroll
        for (int ks = 0; ks < 4; ks++) {
            const uint32_t ka = (32u * ks + acs) ^ xa;
            const uint32_t kb = (32u * ks + bcs) ^ xb;
            uint32_t af[4][4];
#pragma unroll
            for (int m = 0; m < 4; m++) ldsm4(af[m], TBa + m * 2048 + ka);

#pragma unroll
            for (int p = 0; p < 4; p++) {
                uint32_t t4[4];
                ldsm4(t4, TBb + p * 2048 + kb);
                uint32_t b0[2] = {t4[0], t4[1]};
                uint32_t b1[2] = {t4[2], t4[3]};
#pragma unroll
                for (int m = 0; m < 4; m++) {
                    mma16816(acc[m][2 * p],     af[m], b0);
                    mma16816(acc[m][2 * p + 1], af[m], b1);
                }
            }
        }

        // this warp is done with chunk c (stage st)
        if (l == 0) mbar_arrive(emptyb);
        // producer: reuse stage st for chunk c+2 once all 4 warps arrived
        if (tid == 0 && c + 2 < NCH) {
            mbar_wait(emptyb, (c >> 1) & 1);
            issue(c + 2);
        }
    }
    __syncthreads();   // all warps fully done before epilogue reuses smem

    // ---- epilogue: per-row sum/sumsq/top3 ---------------------------------
    float* spart = reinterpret_cast<float*>(dynsmem);   // 128 rows x 2 wn x 10 f
    const int colbase = nblk * BN + wn * 64 + 2 * (l & 3);

#pragma unroll
    for (int m = 0; m < 4; m++) {
#pragma unroll
        for (int h = 0; h < 2; h++) {
            float sum = 0.f, sq = 0.f;
            float v0 = -2.f, v1 = -2.f, v2 = -2.f;
            int   i0 = 0, i1 = 0, i2 = 0;
#pragma unroll
            for (int n = 0; n < 8; n++) {
#pragma unroll
                for (int e = 0; e < 2; e++) {
                    const float v = acc[m][n][2 * h + e];
                    sum += v;
                    sq = fmaf(v, v, sq);
                    top3_ins(v, colbase + 8 * n + e, v0, i0, v1, i1, v2, i2);
                }
            }
#pragma unroll
            for (int o = 1; o <= 2; o <<= 1) {
                float w0 = __shfl_xor_sync(0xffffffffu, v0, o);
                float w1 = __shfl_xor_sync(0xffffffffu, v1, o);
                float w2 = __shfl_xor_sync(0xffffffffu, v2, o);
                int   j0 = __shfl_xor_sync(0xffffffffu, i0, o);
                int   j1 = __shfl_xor_sync(0xffffffffu, i1, o);
                int   j2 = __shfl_xor_sync(0xffffffffu, i2, o);
                sum += __shfl_xor_sync(0xffffffffu, sum, o);
                sq  += __shfl_xor_sync(0xffffffffu, sq, o);
                top3_ins(w0, j0, v0, i0, v1, i1, v2, i2);
                top3_ins(w1, j1, v0, i0, v1, i1, v2, i2);
                top3_ins(w2, j2, v0, i0, v1, i1, v2, i2);
            }
            if ((l & 3) == 0) {
                const int rloc = wm * 64 + 16 * m + (l >> 2) + 8 * h;
                float* p = spart + (rloc * 2 + wn) * 10;
                p[0] = sum; p[1] = sq;
                p[2] = v0;  p[3] = v1;  p[4] = v2;
                p[5] = __int_as_float(i0);
                p[6] = __int_as_float(i1);
                p[7] = __int_as_float(i2);
            }
        }
    }
    __syncthreads();

    {
        float sum = 0.f, sq = 0.f;
        float v0 = -2.f, v1 = -2.f, v2 = -2.f;
        int   i0 = 0, i1 = 0, i2 = 0;
#pragma unroll
        for (int w = 0; w < 2; w++) {
            const float* p = spart + (tid * 2 + w) * 10;
            sum += p[0]; sq += p[1];
            top3_ins(p[2], __float_as_int(p[5]), v0, i0, v1, i1, v2, i2);
            top3_ins(p[3], __float_as_int(p[6]), v0, i0, v1, i1, v2, i2);
            top3_ins(p[4], __float_as_int(p[7]), v0, i0, v1, i1, v2, i2);
        }
        const int gr = bblk * BM + tid;
        const size_t o = (size_t)gr * NBLK + nblk;
        g_ms[o]   = make_float2(sum, sq);
        g_topA[o] = make_float4(v0, __int_as_float(i0), v1, __int_as_float(i1));
        g_topB[o] = make_float2(v2, __int_as_float(i2));
    }
}

// ---------------------------------------------------------------------------
// Kernel 3: per-row reduce -> variance + top-3, then exact fp32 rescore
//           of the 3 candidates + gather values[best]   (fused)
// ---------------------------------------------------------------------------
__global__ void finalize_rescore_kernel(const float* __restrict__ Q,
                                        const float* __restrict__ K,
                                        const float* __restrict__ V,
                                        float* __restrict__ out)
{
    const int row = blockIdx.x;
    const int tid = threadIdx.x;   // 256 == NBLK

    __shared__ float4 sA[256];
    __shared__ float2 sB[256];
    __shared__ float2 sM[256];
    {
        const size_t o = (size_t)row * NBLK + tid;
        sA[tid] = g_topA[o];
        sB[tid] = g_topB[o];
        sM[tid] = g_ms[o];
    }
    __syncthreads();

    for (int off = 128; off > 0; off >>= 1) {
        if (tid < off) {
            float4 a = sA[tid]; float2 a2 = sB[tid];
            float4 b = sA[tid + off]; float2 b2 = sB[tid + off];
            float v0 = a.x, v1 = a.z, v2 = a2.x;
            int   i0 = __float_as_int(a.y), i1 = __float_as_int(a.w),
                  i2 = __float_as_int(a2.y);
            top3_ins(b.x,  __float_as_int(b.y),  v0, i0, v1, i1, v2, i2);
            top3_ins(b.z,  __float_as_int(b.w),  v0, i0, v1, i1, v2, i2);
            top3_ins(b2.x, __float_as_int(b2.y), v0, i0, v1, i1, v2, i2);
            sA[tid] = make_float4(v0, __int_as_float(i0), v1, __int_as_float(i1));
            sB[tid] = make_float2(v2, __int_as_float(i2));
            float2 x = sM[tid], y = sM[tid + off];
            sM[tid] = make_float2(x.x + y.x, x.y + y.y);
        }
        __syncthreads();
    }

    __shared__ int s_cand[3];
    if (tid == 0) {
        const float s = sM[0].x, q2 = sM[0].y;
        g_var[row] = (q2 - s * s / (float)N_) / (float)(N_ - 1);
        s_cand[0] = __float_as_int(sA[0].y);
        s_cand[1] = __float_as_int(sA[0].w);
        s_cand[2] = __float_as_int(sB[0].y);
    }
    __syncthreads();

    const float qi = g_qinv[row];
    float4 q = reinterpret_cast<const float4*>(Q + (size_t)row * D_)[tid];
    q.x *= qi; q.y *= qi; q.z *= qi; q.w *= qi;

    __shared__ float r[3][256];
    __shared__ int sbest;
    const int c0 = s_cand[0], c1 = s_cand[1], c2 = s_cand[2];
    {
        float4 k0 = reinterpret_cast<const float4*>(K + (size_t)c0 * D_)[tid];
        float4 k1 = reinterpret_cast<const float4*>(K + (size_t)c1 * D_)[tid];
        float4 k2 = reinterpret_cast<const float4*>(K + (size_t)c2 * D_)[tid];
        r[0][tid] = (q.x * k0.x + q.y * k0.y + q.z * k0.z + q.w * k0.w) * g_kinv[c0];
        r[1][tid] = (q.x * k1.x + q.y * k1.y + q.z * k1.z + q.w * k1.w) * g_kinv[c1];
        r[2][tid] = (q.x * k2.x + q.y * k2.y + q.z * k2.z + q.w * k2.w) * g_kinv[c2];
    }
    __syncthreads();
    for (int off = 128; off > 0; off >>= 1) {
        if (tid < off) {
            r[0][tid] += r[0][tid + off];
            r[1][tid] += r[1][tid + off];
            r[2][tid] += r[2][tid + off];
        }
        __syncthreads();
    }
    if (tid == 0) {
        const int cands[3] = {c0, c1, c2};
        float bv = r[0][0]; int bi = c0;
        for (int c = 1; c < 3; c++) {
            const float v = r[c][0];
            if (v > bv || (v == bv && cands[c] < bi)) { bv = v; bi = cands[c]; }
        }
        sbest = bi;
    }
    __syncthreads();
    reinterpret_cast<float4*>(out + (size_t)row * D_)[tid] =
        reinterpret_cast<const float4*>(V + (size_t)sbest * D_)[tid];
}

// ---------------------------------------------------------------------------
// Kernel 4: deterministic mean of row variances -> out[B*D]
// ---------------------------------------------------------------------------
__global__ void var_mean_kernel(float* __restrict__ out)
{
    __shared__ float sm[1024];
    const int tid = threadIdx.x;
    sm[tid] = g_var[tid] + g_var[tid + 1024] + g_var[tid + 2048] + g_var[tid + 3072];
    __syncthreads();
    for (int o = 512; o > 0; o >>= 1) {
        if (tid < o) sm[tid] += sm[tid + o];
        __syncthreads();
    }
    if (tid == 0) out[(size_t)B_ * D_] = sm[0] / (float)B_;
}

// ---------------------------------------------------------------------------
extern "C" void kernel_launch(void* const* d_in, const int* in_sizes, int n_in,
                              void* d_out, int out_size)
{
    const float* query  = (const float*)d_in[0];
    const float* keys   = (const float*)d_in[1];
    const float* values = (const float*)d_in[2];
    float* out = (float*)d_out;

    float *qinv, *kinv;
    __half *qh, *kh;
    cudaGetSymbolAddress((void**)&qinv, g_qinv);
    cudaGetSymbolAddress((void**)&kinv, g_kinv);
    cudaGetSymbolAddress((void**)&qh, g_qh);
    cudaGetSymbolAddress((void**)&kh, g_kh);

    cudaFuncSetAttribute(sim_kernel, cudaFuncAttributeMaxDynamicSharedMemorySize, SMEM_DYN);

    prep_kernel<<<B_, 256>>>(query, qinv, qh);
    prep_kernel<<<N_, 256>>>(keys,  kinv, kh);

    sim_kernel<<<dim3(NBLK, BBLK), 128, SMEM_DYN>>>();

    finalize_rescore_kernel<<<B_, 256>>>(query, keys, values, out);
    var_mean_kernel<<<1, 1024>>>(out);
}

// round 17
// speedup vs baseline: 1.1748x; 1.1748x over previous
#include <cuda_runtime.h>
#include <cuda_fp16.h>
#include <cstdint>
#include <math.h>

#define B_   4096
#define N_   32768
#define D_   1024
#define BM   128
#define BN   128
#define KC   64                  // K elems per chunk (64 fp16 = 128 B row)
#define NCH  (D_ / KC)           // 16
#define NBLK (N_ / BN)           // 256
#define BBLK (B_ / BM)           // 32

#define TILE_B   16384           // one chunk-tile: 128 rows x 128 B (swizzled)
#define STAGE_B  (2 * TILE_B)    // A + B chunk = 32 KB
#define MBAR_OFF (2 * STAGE_B)   // 65536
#define SMEM_DYN (MBAR_OFF + 64)

// ---------------- device-global scratch ------------------------------------
// qh/kh stored TILED+SWIZZLED: tile t = (block*16 + chunk) is 16 KB contiguous;
// within a tile: 128 rows x 128 B with SW128 swizzle.
__device__ float  g_qinv[B_];
__device__ float  g_kinv[N_];
__device__ __align__(256) __half g_qh[(size_t)B_ * D_];
__device__ __align__(256) __half g_kh[(size_t)N_ * D_];
__device__ float4 g_topA[(size_t)B_ * NBLK];  // v0,i0,v1,i1
__device__ float2 g_topB[(size_t)B_ * NBLK];  // v2,i2
__device__ float2 g_ms  [(size_t)B_ * NBLK];  // sum,sumsq
__device__ float  g_var[B_];

// ---------------- helpers ---------------------------------------------------
__device__ __forceinline__ uint32_t smem_u32(const void* p) {
    uint32_t a;
    asm("{ .reg .u64 t; cvta.to.shared.u64 t, %1; cvt.u32.u64 %0, t; }" : "=r"(a) : "l"(p));
    return a;
}
__device__ __forceinline__ void ldsm4(uint32_t* r, uint32_t addr) {
    asm volatile("ldmatrix.sync.aligned.m8n8.x4.shared.b16 {%0,%1,%2,%3}, [%4];"
                 : "=r"(r[0]), "=r"(r[1]), "=r"(r[2]), "=r"(r[3]) : "r"(addr));
}
__device__ __forceinline__ void mma16816(float* c, const uint32_t* a, const uint32_t* b) {
    asm volatile("mma.sync.aligned.m16n8k16.row.col.f32.f16.f16.f32 "
                 "{%0,%1,%2,%3}, {%4,%5,%6,%7}, {%8,%9}, {%0,%1,%2,%3};"
                 : "+f"(c[0]), "+f"(c[1]), "+f"(c[2]), "+f"(c[3])
                 : "r"(a[0]), "r"(a[1]), "r"(a[2]), "r"(a[3]), "r"(b[0]), "r"(b[1]));
}
__device__ __forceinline__ void mbar_init(uint32_t a, uint32_t cnt) {
    asm volatile("mbarrier.init.shared.b64 [%0], %1;" :: "r"(a), "r"(cnt) : "memory");
}
__device__ __forceinline__ void mbar_expect_tx(uint32_t a, uint32_t bytes) {
    asm volatile("mbarrier.arrive.expect_tx.shared.b64 _, [%0], %1;"
                 :: "r"(a), "r"(bytes) : "memory");
}
__device__ __forceinline__ void mbar_wait(uint32_t a, uint32_t parity) {
    uint32_t done;
    asm volatile("{\n\t.reg .pred p;\n\t"
                 "mbarrier.try_wait.parity.acquire.cta.shared::cta.b64 p, [%1], %2;\n\t"
                 "selp.b32 %0, 1, 0, p;\n\t}"
                 : "=r"(done) : "r"(a), "r"(parity) : "memory");
    if (!done) {
        asm volatile("{\n\t.reg .pred P;\n\tWL_%=:\n\t"
                     "mbarrier.try_wait.parity.acquire.cta.shared::cta.b64 P, [%0], %1, 0x989680;\n\t"
                     "@P bra.uni WD_%=;\n\tbra.uni WL_%=;\n\tWD_%=:\n\t}"
                     :: "r"(a), "r"(parity) : "memory");
    }
}
__device__ __forceinline__ void bulk_ld(uint32_t dst, const void* src, uint32_t bytes,
                                        uint32_t mbar) {
    asm volatile("cp.async.bulk.shared::cluster.global.mbarrier::complete_tx::bytes "
                 "[%0], [%1], %2, [%3];"
                 :: "r"(dst), "l"(src), "r"(bytes), "r"(mbar) : "memory");
}
__device__ __forceinline__ void top3_ins(float v, int i,
                                         float& v0, int& i0, float& v1, int& i1,
                                         float& v2, int& i2) {
    if (v > v0)      { v2 = v1; i2 = i1; v1 = v0; i1 = i0; v0 = v; i0 = i; }
    else if (v > v1) { v2 = v1; i2 = i1; v1 = v;  i1 = i; }
    else if (v > v2) { v2 = v;  i2 = i; }
}

// ---------------------------------------------------------------------------
// Kernel 1: prep -> inv norm + fp16 normalized rows, TILED+SWIZZLED layout.
//           ONE ROW PER WARP (8 rows/block), shfl-only reduce, no barriers.
// ---------------------------------------------------------------------------
__global__ void prep_kernel(const float* __restrict__ x, float* __restrict__ inv_out,
                            __half* __restrict__ h_out)
{
    const int tid  = threadIdx.x;       // 256
    const int lane = tid & 31;
    const int warp = tid >> 5;          // 0..7
    const int row  = blockIdx.x * 8 + warp;

    const float4* xr = reinterpret_cast<const float4*>(x + (size_t)row * D_);

    float4 v[8];
    float s = 0.f;
#pragma unroll
    for (int i = 0; i < 8; i++) {
        v[i] = xr[lane + 32 * i];
        s += v[i].x * v[i].x + v[i].y * v[i].y + v[i].z * v[i].z + v[i].w * v[i].w;
    }
#pragma unroll
    for (int o = 16; o > 0; o >>= 1) s += __shfl_xor_sync(0xffffffffu, s, o);

    const float inv = 1.0f / fmaxf(sqrtf(s), 1e-12f);
    if (lane == 0) inv_out[row] = inv;

    const int blk  = row >> 7;
    const int rloc = row & 127;
    char* base = (char*)h_out + (size_t)blk * NCH * TILE_B;

#pragma unroll
    for (int i = 0; i < 8; i++) {
        __half2 h0 = __floats2half2_rn(v[i].x * inv, v[i].y * inv);
        __half2 h1 = __floats2half2_rn(v[i].z * inv, v[i].w * inv);
        uint2 pk;
        pk.x = *reinterpret_cast<uint32_t*>(&h0);
        pk.y = *reinterpret_cast<uint32_t*>(&h1);

        const int e0 = 4 * (lane + 32 * i);   // element index in row
        const int c  = e0 >> 6;               // chunk 0..15
        const int j  = e0 & 63;               // col within chunk
        uint32_t boff = (uint32_t)(rloc * 128 + j * 2);
        uint32_t sw   = boff ^ ((boff >> 3) & 0x70);
        *reinterpret_cast<uint2*>(base + (size_t)c * TILE_B + sw) = pk;
    }
}

// ---------------------------------------------------------------------------
// Kernel 2: mma.sync fp16 GEMM, 128x128 tile, 4 warps @ 64x64, 3 CTAs/SM,
//           cp.async.bulk chunk loader + fused top3/sum/sumsq  (R13 verbatim)
// ---------------------------------------------------------------------------
__global__ __launch_bounds__(128, 3)
void sim_kernel()
{
    extern __shared__ char dynsmem[];
    const uint32_t sbase = smem_u32(dynsmem);

    const int tid = threadIdx.x;    // 128
    const int l   = tid & 31;
    const int wid = tid >> 5;       // 0..3
    const int wm  = wid >> 1;       // 0..1 -> 64-row half
    const int wn  = wid & 1;        // 0..1 -> 64-col half
    const int nblk = blockIdx.x;
    const int bblk = blockIdx.y;

    const char* srcA = (const char*)g_qh + (size_t)bblk * NCH * TILE_B;
    const char* srcB = (const char*)g_kh + (size_t)nblk * NCH * TILE_B;

    const uint32_t mb0 = sbase + MBAR_OFF;
    const uint32_t mb1 = sbase + MBAR_OFF + 8;

    if (tid == 0) { mbar_init(mb0, 1); mbar_init(mb1, 1); }
    __syncthreads();

    if (tid == 0) {
        mbar_expect_tx(mb0, STAGE_B);
        bulk_ld(sbase,          srcA, TILE_B, mb0);
        bulk_ld(sbase + TILE_B, srcB, TILE_B, mb0);
    }

    // ---- per-lane ldmatrix offsets ----------------------------------------
    const uint32_t rowA = l & 15;
    const uint32_t acs  = (l >> 4) * 16;
    const uint32_t xa   = (rowA & 7) << 4;
    const uint32_t aoff = rowA * 128 + (uint32_t)wm * 8192;   // wm*64 rows

    const uint32_t rowB = (l & 7) + ((l >> 4) << 3);
    const uint32_t bcs  = ((l >> 3) & 1) * 16;
    const uint32_t xb   = (rowB & 7) << 4;
    const uint32_t boff = rowB * 128 + (uint32_t)wn * 8192;   // wn*64 rows

    float acc[4][8][4];
#pragma unroll
    for (int m = 0; m < 4; m++)
#pragma unroll
        for (int n = 0; n < 8; n++)
#pragma unroll
            for (int e = 0; e < 4; e++) acc[m][n][e] = 0.f;

    int par[2] = {0, 0};

    for (int c = 0; c < NCH; c++) {
        const int st = c & 1;
        const uint32_t mb = st ? mb1 : mb0;

        // kick next chunk into the other stage (free since iter c-1's barrier)
        if (tid == 0 && c + 1 < NCH) {
            const uint32_t nst = sbase + (st ^ 1) * STAGE_B;
            const uint32_t mbn = (st ^ 1) ? mb1 : mb0;
            mbar_expect_tx(mbn, STAGE_B);
            bulk_ld(nst,          srcA + (size_t)(c + 1) * TILE_B, TILE_B, mbn);
            bulk_ld(nst + TILE_B, srcB + (size_t)(c + 1) * TILE_B, TILE_B, mbn);
        }

        mbar_wait(mb, par[st]);
        par[st] ^= 1;

        const uint32_t TBa = sbase + st * STAGE_B + aoff;
        const uint32_t TBb = sbase + st * STAGE_B + TILE_B + boff;

#pragma unroll
        for (int ks = 0; ks < 4; ks++) {
            const uint32_t ka = (32u * ks + acs) ^ xa;
            const uint32_t kb = (32u * ks + bcs) ^ xb;
            uint32_t af[4][4];
#pragma unroll
            for (int m = 0; m < 4; m++) ldsm4(af[m], TBa + m * 2048 + ka);

#pragma unroll
            for (int p = 0; p < 4; p++) {
                uint32_t t4[4];
                ldsm4(t4, TBb + p * 2048 + kb);
                uint32_t b0[2] = {t4[0], t4[1]};
                uint32_t b1[2] = {t4[2], t4[3]};
#pragma unroll
                for (int m = 0; m < 4; m++) {
                    mma16816(acc[m][2 * p],     af[m], b0);
                    mma16816(acc[m][2 * p + 1], af[m], b1);
                }
            }
        }
        __syncthreads();   // all warps done with stage st -> safe to overwrite
    }

    // ---- epilogue: per-row sum/sumsq/top3 ---------------------------------
    float* spart = reinterpret_cast<float*>(dynsmem);   // 128 rows x 2 wn x 10 f
    const int colbase = nblk * BN + wn * 64 + 2 * (l & 3);

#pragma unroll
    for (int m = 0; m < 4; m++) {
#pragma unroll
        for (int h = 0; h < 2; h++) {
            float sum = 0.f, sq = 0.f;
            float v0 = -2.f, v1 = -2.f, v2 = -2.f;
            int   i0 = 0, i1 = 0, i2 = 0;
#pragma unroll
            for (int n = 0; n < 8; n++) {
#pragma unroll
                for (int e = 0; e < 2; e++) {
                    const float v = acc[m][n][2 * h + e];
                    sum += v;
                    sq = fmaf(v, v, sq);
                    top3_ins(v, colbase + 8 * n + e, v0, i0, v1, i1, v2, i2);
                }
            }
#pragma unroll
            for (int o = 1; o <= 2; o <<= 1) {
                float w0 = __shfl_xor_sync(0xffffffffu, v0, o);
                float w1 = __shfl_xor_sync(0xffffffffu, v1, o);
                float w2 = __shfl_xor_sync(0xffffffffu, v2, o);
                int   j0 = __shfl_xor_sync(0xffffffffu, i0, o);
                int   j1 = __shfl_xor_sync(0xffffffffu, i1, o);
                int   j2 = __shfl_xor_sync(0xffffffffu, i2, o);
                sum += __shfl_xor_sync(0xffffffffu, sum, o);
                sq  += __shfl_xor_sync(0xffffffffu, sq, o);
                top3_ins(w0, j0, v0, i0, v1, i1, v2, i2);
                top3_ins(w1, j1, v0, i0, v1, i1, v2, i2);
                top3_ins(w2, j2, v0, i0, v1, i1, v2, i2);
            }
            if ((l & 3) == 0) {
                const int rloc = wm * 64 + 16 * m + (l >> 2) + 8 * h;
                float* p = spart + (rloc * 2 + wn) * 10;
                p[0] = sum; p[1] = sq;
                p[2] = v0;  p[3] = v1;  p[4] = v2;
                p[5] = __int_as_float(i0);
                p[6] = __int_as_float(i1);
                p[7] = __int_as_float(i2);
            }
        }
    }
    __syncthreads();

    {
        float sum = 0.f, sq = 0.f;
        float v0 = -2.f, v1 = -2.f, v2 = -2.f;
        int   i0 = 0, i1 = 0, i2 = 0;
#pragma unroll
        for (int w = 0; w < 2; w++) {
            const float* p = spart + (tid * 2 + w) * 10;
            sum += p[0]; sq += p[1];
            top3_ins(p[2], __float_as_int(p[5]), v0, i0, v1, i1, v2, i2);
            top3_ins(p[3], __float_as_int(p[6]), v0, i0, v1, i1, v2, i2);
            top3_ins(p[4], __float_as_int(p[7]), v0, i0, v1, i1, v2, i2);
        }
        const int gr = bblk * BM + tid;
        const size_t o = (size_t)gr * NBLK + nblk;
        g_ms[o]   = make_float2(sum, sq);
        g_topA[o] = make_float4(v0, __int_as_float(i0), v1, __int_as_float(i1));
        g_topB[o] = make_float2(v2, __int_as_float(i2));
    }
}

// ---------------------------------------------------------------------------
// Kernel 3: per-row reduce -> variance + top-3, then exact fp32 rescore
//           of the 3 candidates + gather values[best]   (fused)
// ---------------------------------------------------------------------------
__global__ void finalize_rescore_kernel(const float* __restrict__ Q,
                                        const float* __restrict__ K,
                                        const float* __restrict__ V,
                                        float* __restrict__ out)
{
    const int row = blockIdx.x;
    const int tid = threadIdx.x;   // 256 == NBLK

    __shared__ float4 sA[256];
    __shared__ float2 sB[256];
    __shared__ float2 sM[256];
    {
        const size_t o = (size_t)row * NBLK + tid;
        sA[tid] = g_topA[o];
        sB[tid] = g_topB[o];
        sM[tid] = g_ms[o];
    }
    __syncthreads();

    for (int off = 128; off > 0; off >>= 1) {
        if (tid < off) {
            float4 a = sA[tid]; float2 a2 = sB[tid];
            float4 b = sA[tid + off]; float2 b2 = sB[tid + off];
            float v0 = a.x, v1 = a.z, v2 = a2.x;
            int   i0 = __float_as_int(a.y), i1 = __float_as_int(a.w),
                  i2 = __float_as_int(a2.y);
            top3_ins(b.x,  __float_as_int(b.y),  v0, i0, v1, i1, v2, i2);
            top3_ins(b.z,  __float_as_int(b.w),  v0, i0, v1, i1, v2, i2);
            top3_ins(b2.x, __float_as_int(b2.y), v0, i0, v1, i1, v2, i2);
            sA[tid] = make_float4(v0, __int_as_float(i0), v1, __int_as_float(i1));
            sB[tid] = make_float2(v2, __int_as_float(i2));
            float2 x = sM[tid], y = sM[tid + off];
            sM[tid] = make_float2(x.x + y.x, x.y + y.y);
        }
        __syncthreads();
    }

    __shared__ int s_cand[3];
    if (tid == 0) {
        const float s = sM[0].x, q2 = sM[0].y;
        g_var[row] = (q2 - s * s / (float)N_) / (float)(N_ - 1);
        s_cand[0] = __float_as_int(sA[0].y);
        s_cand[1] = __float_as_int(sA[0].w);
        s_cand[2] = __float_as_int(sB[0].y);
    }
    __syncthreads();

    const float qi = g_qinv[row];
    float4 q = reinterpret_cast<const float4*>(Q + (size_t)row * D_)[tid];
    q.x *= qi; q.y *= qi; q.z *= qi; q.w *= qi;

    __shared__ float r[3][256];
    __shared__ int sbest;
    const int c0 = s_cand[0], c1 = s_cand[1], c2 = s_cand[2];
    {
        float4 k0 = reinterpret_cast<const float4*>(K + (size_t)c0 * D_)[tid];
        float4 k1 = reinterpret_cast<const float4*>(K + (size_t)c1 * D_)[tid];
        float4 k2 = reinterpret_cast<const float4*>(K + (size_t)c2 * D_)[tid];
        r[0][tid] = (q.x * k0.x + q.y * k0.y + q.z * k0.z + q.w * k0.w) * g_kinv[c0];
        r[1][tid] = (q.x * k1.x + q.y * k1.y + q.z * k1.z + q.w * k1.w) * g_kinv[c1];
        r[2][tid] = (q.x * k2.x + q.y * k2.y + q.z * k2.z + q.w * k2.w) * g_kinv[c2];
    }
    __syncthreads();
    for (int off = 128; off > 0; off >>= 1) {
        if (tid < off) {
            r[0][tid] += r[0][tid + off];
            r[1][tid] += r[1][tid + off];
            r[2][tid] += r[2][tid + off];
        }
        __syncthreads();
    }
    if (tid == 0) {
        const int cands[3] = {c0, c1, c2};
        float bv = r[0][0]; int bi = c0;
        for (int c = 1; c < 3; c++) {
            const float v = r[c][0];
            if (v > bv || (v == bv && cands[c] < bi)) { bv = v; bi = cands[c]; }
        }
        sbest = bi;
    }
    __syncthreads();
    reinterpret_cast<float4*>(out + (size_t)row * D_)[tid] =
        reinterpret_cast<const float4*>(V + (size_t)sbest * D_)[tid];
}

// ---------------------------------------------------------------------------
// Kernel 4: deterministic mean of row variances -> out[B*D]
// ---------------------------------------------------------------------------
__global__ void var_mean_kernel(float* __restrict__ out)
{
    __shared__ float sm[1024];
    const int tid = threadIdx.x;
    sm[tid] = g_var[tid] + g_var[tid + 1024] + g_var[tid + 2048] + g_var[tid + 3072];
    __syncthreads();
    for (int o = 512; o > 0; o >>= 1) {
        if (tid < o) sm[tid] += sm[tid + o];
        __syncthreads();
    }
    if (tid == 0) out[(size_t)B_ * D_] = sm[0] / (float)B_;
}

// ---------------------------------------------------------------------------
extern "C" void kernel_launch(void* const* d_in, const int* in_sizes, int n_in,
                              void* d_out, int out_size)
{
    const float* query  = (const float*)d_in[0];
    const float* keys   = (const float*)d_in[1];
    const float* values = (const float*)d_in[2];
    float* out = (float*)d_out;

    float *qinv, *kinv;
    __half *qh, *kh;
    cudaGetSymbolAddress((void**)&qinv, g_qinv);
    cudaGetSymbolAddress((void**)&kinv, g_kinv);
    cudaGetSymbolAddress((void**)&qh, g_qh);
    cudaGetSymbolAddress((void**)&kh, g_kh);

    cudaFuncSetAttribute(sim_kernel, cudaFuncAttributeMaxDynamicSharedMemorySize, SMEM_DYN);

    prep_kernel<<<B_ / 8, 256>>>(query, qinv, qh);
    prep_kernel<<<N_ / 8, 256>>>(keys,  kinv, kh);

    sim_kernel<<<dim3(NBLK, BBLK), 128, SMEM_DYN>>>();

    finalize_rescore_kernel<<<B_, 256>>>(query, keys, values, out);
    var_mean_kernel<<<1, 1024>>>(out);
}